// round 13
// baseline (speedup 1.0000x reference)
#include <cuda_runtime.h>

// bi_LSTM_47218870453093 — FINAL (frozen).
//
// Output = softmax over a length-1 axis == exactly 1.0f for every element,
// independent of all inputs (R1, rel_err == 0.0 exactly on every run). The
// entire bidirectional LSTM is dead code w.r.t. the output; this kernel is
// the exact constant-fold.
//
// Measured cost model (R1-R12):
//   real store work:  16KB ~= 0.1us
//   launch/replay:    4.3-5.1us, CODE-INVARIANT — byte-identical source
//                     measured {4.32, 4.42, 4.45, 4.58, 4.58, 4.77, 4.80,
//                     4.86, 4.99, 5.02}us across ten runs (mean 4.68).
//                     R12 drew a NEW SESSION MINIMUM (4.32us) from
//                     unchanged code — direct proof the per-run number is
//                     a noise draw, not a property of the cubin.
// => single minimal kernel node is the floor. No structural lever remains:
//    0 graph nodes is rejected by the harness (R0); a memset node is the
//    same dispatch class; grid shape and body complexity directly measured
//    as no-ops. Held frozen.

__global__ __launch_bounds__(256, 1) void fill_ones_1store(float4* __restrict__ out) {
    out[blockIdx.x * 256 + threadIdx.x] =
        make_float4(1.0f, 1.0f, 1.0f, 1.0f);
}

// Generic fallback (defensive; out_size is 4096 for this problem).
__global__ void fill_ones_generic(float* __restrict__ out, int n) {
    int i = blockIdx.x * blockDim.x + threadIdx.x;
    if (i < n) out[i] = 1.0f;
}

extern "C" void kernel_launch(void* const* d_in, const int* in_sizes, int n_in,
                              void* d_out, int out_size) {
    (void)d_in; (void)in_sizes; (void)n_in;
    if (out_size == 4096) {
        // 4096 floats = 1024 float4; 4 blocks x 256 threads, 1 store each.
        fill_ones_1store<<<4, 256>>>(reinterpret_cast<float4*>(d_out));
    } else {
        int threads = 256;
        int blocks = (out_size + threads - 1) / threads;
        if (blocks < 1) blocks = 1;
        fill_ones_generic<<<blocks, threads>>>(reinterpret_cast<float*>(d_out), out_size);
    }
}

// round 14
// speedup vs baseline: 1.1481x; 1.1481x over previous
#include <cuda_runtime.h>

// bi_LSTM_47218870453093 — FINAL (frozen).
//
// Output = softmax over a length-1 axis == exactly 1.0f for every element,
// independent of all inputs (R1, rel_err == 0.0 exactly on every run). The
// entire bidirectional LSTM is dead code w.r.t. the output; this kernel is
// the exact constant-fold.
//
// Measured cost model (R1-R13):
//   real store work:  16KB ~= 0.1us
//   launch/replay:    4.3-5.1us, CODE-INVARIANT — byte-identical source
//                     measured {4.32, 4.42, 4.45, 4.58, 4.58, 4.77, 4.80,
//                     4.86, 4.96, 4.99, 5.02}us across eleven runs (mean
//                     4.70, sigma 0.23). R12 drew the session minimum and
//                     R13 regressed to the mean with unchanged code —
//                     the per-run number is a noise draw, not a property
//                     of the cubin.
// => single minimal kernel node is the floor. No structural lever remains:
//    0 graph nodes is rejected by the harness (R0); a memset node is the
//    same dispatch class; grid shape and body complexity directly measured
//    as no-ops. Held frozen.

__global__ __launch_bounds__(256, 1) void fill_ones_1store(float4* __restrict__ out) {
    out[blockIdx.x * 256 + threadIdx.x] =
        make_float4(1.0f, 1.0f, 1.0f, 1.0f);
}

// Generic fallback (defensive; out_size is 4096 for this problem).
__global__ void fill_ones_generic(float* __restrict__ out, int n) {
    int i = blockIdx.x * blockDim.x + threadIdx.x;
    if (i < n) out[i] = 1.0f;
}

extern "C" void kernel_launch(void* const* d_in, const int* in_sizes, int n_in,
                              void* d_out, int out_size) {
    (void)d_in; (void)in_sizes; (void)n_in;
    if (out_size == 4096) {
        // 4096 floats = 1024 float4; 4 blocks x 256 threads, 1 store each.
        fill_ones_1store<<<4, 256>>>(reinterpret_cast<float4*>(d_out));
    } else {
        int threads = 256;
        int blocks = (out_size + threads - 1) / threads;
        if (blocks < 1) blocks = 1;
        fill_ones_generic<<<blocks, threads>>>(reinterpret_cast<float*>(d_out), out_size);
    }
}